// round 16
// baseline (speedup 1.0000x reference)
#include <cuda_runtime.h>
#include <cuda_bf16.h>
#include <math.h>

// Problem constants
#define N_NODES 100000
#define N_EDGES 1600000
#define DFEAT   128
#define NCLS    40

// ---------------------------------------------------------------------------
// Device scratch (no allocations allowed)
// ---------------------------------------------------------------------------
__device__ __align__(16) float g_aggr[N_NODES * DFEAT];
__device__ __align__(16) float g_h   [N_NODES * DFEAT];
__device__ __align__(16) float g_h2  [N_NODES * DFEAT];
__device__ int   g_deg   [N_NODES];
__device__ float g_deginv[N_NODES];
__device__ int   g_rowptr[N_NODES + 1];
__device__ int   g_cursor[N_NODES];
__device__ int   g_csr   [N_EDGES];
__device__ int   g_part  [128];
__device__ int   g_is64;   // 1 if edge_index buffer is int64, 0 if int32

#define SCAN_NBLK ((N_NODES + 1023) / 1024)   // 98

__device__ __forceinline__ int edge_val(const int* ei, int is64, int idx) {
    if (is64) return (int)((const long long*)ei)[idx];
    return ei[idx];
}

// ---------------------------------------------------------------------------
// zero deg + edge-index dtype detection (block 0 detects)
// ---------------------------------------------------------------------------
__global__ void zero_detect_kernel(const int* __restrict__ ei32) {
    int i = blockIdx.x * blockDim.x + threadIdx.x;
    if (i < N_NODES) g_deg[i] = 0;
    if (blockIdx.x == 0) {
        __shared__ int sOr;
        if (threadIdx.x == 0) sOr = 0;
        __syncthreads();
        int v = 0;
        for (int k = threadIdx.x; k < 8192; k += blockDim.x)
            v |= ei32[2 * k + 1];
        atomicOr(&sOr, v);
        __syncthreads();
        if (threadIdx.x == 0) g_is64 = (sOr == 0) ? 1 : 0;
    }
}

__global__ void count_deg_kernel(const int* __restrict__ ei) {
    int e = blockIdx.x * blockDim.x + threadIdx.x;
    if (e < N_EDGES) {
        int is64 = g_is64;
        int dst = edge_val(ei, is64, N_EDGES + e);
        if ((unsigned)dst < (unsigned)N_NODES)
            atomicAdd(&g_deg[dst], 1);
    }
}

// Per-block (1024 elems) exclusive scan into g_rowptr, block totals to g_part.
__global__ void scan_blocks_kernel() {
    __shared__ int wsum[8];
    int tid  = threadIdx.x;
    int base = blockIdx.x * 1024 + tid * 4;
    int v[4];
    int s = 0;
#pragma unroll
    for (int j = 0; j < 4; j++) {
        v[j] = (base + j < N_NODES) ? g_deg[base + j] : 0;
        s += v[j];
    }
    int lane = tid & 31, w = tid >> 5;
    int inc = s;
#pragma unroll
    for (int o = 1; o < 32; o <<= 1) {
        int y = __shfl_up_sync(0xffffffffu, inc, o);
        if (lane >= o) inc += y;
    }
    if (lane == 31) wsum[w] = inc;
    __syncthreads();
    if (w == 0) {
        int t = (lane < 8) ? wsum[lane] : 0;
#pragma unroll
        for (int o = 1; o < 8; o <<= 1) {
            int y = __shfl_up_sync(0xffffffffu, t, o);
            if (lane >= o) t += y;
        }
        if (lane < 8) wsum[lane] = t;
    }
    __syncthreads();
    int excl = inc - s + (w ? wsum[w - 1] : 0);
#pragma unroll
    for (int j = 0; j < 4; j++) {
        if (base + j < N_NODES) g_rowptr[base + j] = excl;
        excl += v[j];
    }
    if (tid == 0) g_part[blockIdx.x] = wsum[7];
}

// Add block offsets (each block redundantly scans the 98 partials in smem);
// init cursor; compute deg_inv; set rowptr[N_NODES].
__global__ void scan_add_kernel() {
    __shared__ int sp[SCAN_NBLK];
    int tid = threadIdx.x;
    if (tid < SCAN_NBLK) sp[tid] = g_part[tid];
    __syncthreads();
    if (tid == 0) {
        int c = 0;
#pragma unroll 1
        for (int j = 0; j < SCAN_NBLK; j++) { int t = sp[j]; sp[j] = c; c += t; }
    }
    __syncthreads();
    int i = blockIdx.x * blockDim.x + tid;
    if (i < N_NODES) {
        int d = g_deg[i];
        int r = g_rowptr[i] + sp[i >> 10];
        g_rowptr[i] = r;
        g_cursor[i] = r;
        g_deginv[i] = 1.0f / (float)max(d, 1);
        if (i == N_NODES - 1) g_rowptr[N_NODES] = r + d;
    }
}

__global__ void fill_csr_kernel(const int* __restrict__ ei) {
    int e = blockIdx.x * blockDim.x + threadIdx.x;
    if (e < N_EDGES) {
        int is64 = g_is64;
        int dst = edge_val(ei, is64, N_EDGES + e);
        if ((unsigned)dst < (unsigned)N_NODES) {
            int src = edge_val(ei, is64, e);
            if ((unsigned)src >= (unsigned)N_NODES) src = 0;
            int pos = atomicAdd(&g_cursor[dst], 1);
            g_csr[pos] = src;
        }
    }
}

// ---------------------------------------------------------------------------
// Feature source selection
// ---------------------------------------------------------------------------
__device__ __forceinline__ const float* pick_feat(const float* ext, int sel) {
    return sel == 0 ? ext : (sel == 1 ? g_h : g_h2);
}

// ---------------------------------------------------------------------------
// Mean aggregation: one warp per node, lane owns 4 contiguous floats.
// Inner loop processes 8 edges per batch -> 8 independent LDG.128 in flight.
// ---------------------------------------------------------------------------
__global__ void aggregate_kernel(const float* __restrict__ feat_ext, int sel) {
    int gw = (blockIdx.x * blockDim.x + threadIdx.x) >> 5;
    if (gw >= N_NODES) return;
    const float* feat = pick_feat(feat_ext, sel);
    int lane = threadIdx.x & 31;
    int s   = g_rowptr[gw];
    int deg = g_rowptr[gw + 1] - s;
    float4 acc = make_float4(0.f, 0.f, 0.f, 0.f);
    const float4* f4 = (const float4*)feat;
    for (int b = 0; b < deg; b += 32) {
        int idx = 0;
        if (b + lane < deg) idx = g_csr[s + b + lane];
        int cnt = min(32, deg - b);
        int t = 0;
        for (; t + 8 <= cnt; t += 8) {
            int s0 = __shfl_sync(0xffffffffu, idx, t);
            int s1 = __shfl_sync(0xffffffffu, idx, t + 1);
            int s2 = __shfl_sync(0xffffffffu, idx, t + 2);
            int s3 = __shfl_sync(0xffffffffu, idx, t + 3);
            int s4 = __shfl_sync(0xffffffffu, idx, t + 4);
            int s5 = __shfl_sync(0xffffffffu, idx, t + 5);
            int s6 = __shfl_sync(0xffffffffu, idx, t + 6);
            int s7 = __shfl_sync(0xffffffffu, idx, t + 7);
            float4 v0 = __ldg(&f4[s0 * 32 + lane]);
            float4 v1 = __ldg(&f4[s1 * 32 + lane]);
            float4 v2 = __ldg(&f4[s2 * 32 + lane]);
            float4 v3 = __ldg(&f4[s3 * 32 + lane]);
            float4 v4 = __ldg(&f4[s4 * 32 + lane]);
            float4 v5 = __ldg(&f4[s5 * 32 + lane]);
            float4 v6 = __ldg(&f4[s6 * 32 + lane]);
            float4 v7 = __ldg(&f4[s7 * 32 + lane]);
            // pairwise tree to shorten the FADD dependency chain
            float4 a0, a1, a2, a3, b0, b1;
            a0.x = v0.x + v1.x; a0.y = v0.y + v1.y; a0.z = v0.z + v1.z; a0.w = v0.w + v1.w;
            a1.x = v2.x + v3.x; a1.y = v2.y + v3.y; a1.z = v2.z + v3.z; a1.w = v2.w + v3.w;
            a2.x = v4.x + v5.x; a2.y = v4.y + v5.y; a2.z = v4.z + v5.z; a2.w = v4.w + v5.w;
            a3.x = v6.x + v7.x; a3.y = v6.y + v7.y; a3.z = v6.z + v7.z; a3.w = v6.w + v7.w;
            b0.x = a0.x + a1.x; b0.y = a0.y + a1.y; b0.z = a0.z + a1.z; b0.w = a0.w + a1.w;
            b1.x = a2.x + a3.x; b1.y = a2.y + a3.y; b1.z = a2.z + a3.z; b1.w = a2.w + a3.w;
            acc.x += b0.x + b1.x; acc.y += b0.y + b1.y;
            acc.z += b0.z + b1.z; acc.w += b0.w + b1.w;
        }
        for (; t < cnt; t++) {
            int sv = __shfl_sync(0xffffffffu, idx, t);
            float4 v = __ldg(&f4[sv * 32 + lane]);
            acc.x += v.x; acc.y += v.y; acc.z += v.z; acc.w += v.w;
        }
    }
    float di = g_deginv[gw];
    acc.x *= di; acc.y *= di; acc.z *= di; acc.w *= di;
    ((float4*)g_aggr)[gw * 32 + lane] = acc;
}

// ---------------------------------------------------------------------------
// tf32 mma (raw fp32 bits fed as tf32: HW ignores low mantissa bits)
// ---------------------------------------------------------------------------
__device__ __forceinline__ void mma_tf32(float c[4], const float a[4], const float b[2]) {
    asm volatile(
        "mma.sync.aligned.m16n8k8.row.col.f32.tf32.tf32.f32 "
        "{%0,%1,%2,%3}, {%4,%5,%6,%7}, {%8,%9}, {%0,%1,%2,%3};\n"
        : "+f"(c[0]), "+f"(c[1]), "+f"(c[2]), "+f"(c[3])
        : "r"(__float_as_uint(a[0])), "r"(__float_as_uint(a[1])),
          "r"(__float_as_uint(a[2])), "r"(__float_as_uint(a[3])),
          "r"(__float_as_uint(b[0])), "r"(__float_as_uint(b[1])));
}

// ---------------------------------------------------------------------------
// Tensor-core dual GEMM, D=128 -> 128 as one K=256 GEMM (pipelined fills).
// ---------------------------------------------------------------------------
__global__ __launch_bounds__(256) void dual_gemm128_tc_kernel(
    const float* __restrict__ Ax_ext, int ax_sel,
    const float* __restrict__ Wl, const float* __restrict__ Wr,
    const float* __restrict__ bias, int out_sel)
{
    __shared__ float sA[128 * 36];
    __shared__ float sB[32 * 132];

    const float* Ax  = pick_feat(Ax_ext, ax_sel);
    float* out = (out_sel == 1) ? g_h : g_h2;

    int tid  = threadIdx.x;
    int wid  = tid >> 5;
    int lane = tid & 31;
    int wm   = wid & 1;
    int wn   = wid >> 1;
    int tg   = lane & 3;
    int g    = lane >> 2;
    int rowBase = blockIdx.x * 128;

    int ra[4], ca[4], rb[4], cb[4];
#pragma unroll
    for (int i = 0; i < 4; i++) {
        int q = tid + i * 256;
        ra[i] = q >> 3; ca[i] = q & 7;
        rb[i] = q >> 5; cb[i] = q & 31;
    }

    float c[4][4][4];
#pragma unroll
    for (int mf = 0; mf < 4; mf++)
#pragma unroll
        for (int nf = 0; nf < 4; nf++)
#pragma unroll
            for (int i = 0; i < 4; i++) c[mf][nf][i] = 0.f;

    float4 pa[4], pb[4];
    {
#pragma unroll
        for (int i = 0; i < 4; i++) {
            int row = rowBase + ra[i];
            pa[i] = make_float4(0.f, 0.f, 0.f, 0.f);
            if (row < N_NODES)
                pa[i] = __ldg((const float4*)(g_aggr + row * 128) + ca[i]);
            pb[i] = __ldg((const float4*)(Wl + rb[i] * 128) + cb[i]);
        }
    }

    for (int kc = 0; kc < 256; kc += 32) {
#pragma unroll
        for (int i = 0; i < 4; i++) {
            *(float4*)&sA[ra[i] * 36 + ca[i] * 4] = pa[i];
            *(float4*)&sB[rb[i] * 132 + cb[i] * 4] = pb[i];
        }
        __syncthreads();

        int kn = kc + 32;
        if (kn < 256) {
            const float* srcA = (kn < 128) ? g_aggr : Ax;
            const float* srcW = (kn < 128) ? Wl : Wr;
            int knl = kn & 127;
#pragma unroll
            for (int i = 0; i < 4; i++) {
                int row = rowBase + ra[i];
                pa[i] = make_float4(0.f, 0.f, 0.f, 0.f);
                if (row < N_NODES)
                    pa[i] = __ldg((const float4*)(srcA + row * 128 + knl) + ca[i]);
                pb[i] = __ldg((const float4*)(srcW + (knl + rb[i]) * 128) + cb[i]);
            }
        }

#pragma unroll
        for (int kk = 0; kk < 32; kk += 8) {
            float a[4][4];
#pragma unroll
            for (int mf = 0; mf < 4; mf++) {
                int r0 = (wm * 64 + mf * 16 + g) * 36 + kk + tg;
                a[mf][0] = sA[r0];
                a[mf][1] = sA[r0 + 8 * 36];
                a[mf][2] = sA[r0 + 4];
                a[mf][3] = sA[r0 + 8 * 36 + 4];
            }
            float b[4][2];
#pragma unroll
            for (int nf = 0; nf < 4; nf++) {
                int col = wn * 32 + nf * 8 + g;
                b[nf][0] = sB[(kk + tg) * 132 + col];
                b[nf][1] = sB[(kk + tg + 4) * 132 + col];
            }
#pragma unroll
            for (int mf = 0; mf < 4; mf++)
#pragma unroll
                for (int nf = 0; nf < 4; nf++)
                    mma_tf32(c[mf][nf], a[mf], b[nf]);
        }
        __syncthreads();
    }

#pragma unroll
    for (int mf = 0; mf < 4; mf++) {
        int row0 = rowBase + wm * 64 + mf * 16 + g;
#pragma unroll
        for (int nf = 0; nf < 4; nf++) {
            int col = wn * 32 + nf * 8 + 2 * tg;
            float2 bv = __ldg((const float2*)(bias + col));
            if (row0 < N_NODES) {
                float2 o;
                o.x = fmaxf(c[mf][nf][0] + bv.x, 0.f);
                o.y = fmaxf(c[mf][nf][1] + bv.y, 0.f);
                *(float2*)(out + row0 * 128 + col) = o;
            }
            if (row0 + 8 < N_NODES) {
                float2 o;
                o.x = fmaxf(c[mf][nf][2] + bv.x, 0.f);
                o.y = fmaxf(c[mf][nf][3] + bv.y, 0.f);
                *(float2*)(out + (row0 + 8) * 128 + col) = o;
            }
        }
    }
}

// ---------------------------------------------------------------------------
// Tensor-core dual GEMM, D=128 -> 40 + fused log_softmax (final layer).
// ---------------------------------------------------------------------------
__global__ __launch_bounds__(256) void dual_gemm40_tc_lsm_kernel(
    const float* __restrict__ Wl, const float* __restrict__ Wr,
    const float* __restrict__ bias, float* __restrict__ out)
{
    __shared__ float sA[128 * 36];
    __shared__ float sB[32 * 44];
    __shared__ float sb[40];

    int tid  = threadIdx.x;
    int wid  = tid >> 5;
    int lane = tid & 31;
    int tg   = lane & 3;
    int g    = lane >> 2;
    int rowBase = blockIdx.x * 128;
    if (tid < 40) sb[tid] = __ldg(bias + tid);

    int ra[4], ca[4];
#pragma unroll
    for (int i = 0; i < 4; i++) {
        int q = tid + i * 256;
        ra[i] = q >> 3; ca[i] = q & 7;
    }
    int qk[5], qj[5];
#pragma unroll
    for (int i = 0; i < 5; i++) {
        int q = tid + i * 256;
        qk[i] = q / 40; qj[i] = q - qk[i] * 40;
    }

    float c[5][4];
#pragma unroll
    for (int nf = 0; nf < 5; nf++)
#pragma unroll
        for (int i = 0; i < 4; i++) c[nf][i] = 0.f;

    float4 pa[4];
    float  pbv[5];
    {
#pragma unroll
        for (int i = 0; i < 4; i++) {
            int row = rowBase + ra[i];
            pa[i] = make_float4(0.f, 0.f, 0.f, 0.f);
            if (row < N_NODES)
                pa[i] = __ldg((const float4*)(g_aggr + row * 128) + ca[i]);
        }
#pragma unroll
        for (int i = 0; i < 5; i++)
            pbv[i] = __ldg(Wl + qk[i] * 40 + qj[i]);
    }

    for (int kc = 0; kc < 256; kc += 32) {
#pragma unroll
        for (int i = 0; i < 4; i++)
            *(float4*)&sA[ra[i] * 36 + ca[i] * 4] = pa[i];
#pragma unroll
        for (int i = 0; i < 5; i++)
            sB[qk[i] * 44 + qj[i]] = pbv[i];
        __syncthreads();

        int kn = kc + 32;
        if (kn < 256) {
            const float* srcA = (kn < 128) ? g_aggr : g_h2;
            const float* srcW = (kn < 128) ? Wl : Wr;
            int knl = kn & 127;
#pragma unroll
            for (int i = 0; i < 4; i++) {
                int row = rowBase + ra[i];
                pa[i] = make_float4(0.f, 0.f, 0.f, 0.f);
                if (row < N_NODES)
                    pa[i] = __ldg((const float4*)(srcA + row * 128 + knl) + ca[i]);
            }
#pragma unroll
            for (int i = 0; i < 5; i++)
                pbv[i] = __ldg(srcW + (knl + qk[i]) * 40 + qj[i]);
        }

#pragma unroll
        for (int kk = 0; kk < 32; kk += 8) {
            float a[4];
            {
                int r0 = (wid * 16 + g) * 36 + kk + tg;
                a[0] = sA[r0];
                a[1] = sA[r0 + 8 * 36];
                a[2] = sA[r0 + 4];
                a[3] = sA[r0 + 8 * 36 + 4];
            }
            float b[5][2];
#pragma unroll
            for (int nf = 0; nf < 5; nf++) {
                int col = nf * 8 + g;
                b[nf][0] = sB[(kk + tg) * 44 + col];
                b[nf][1] = sB[(kk + tg + 4) * 44 + col];
            }
#pragma unroll
            for (int nf = 0; nf < 5; nf++)
                mma_tf32(c[nf], a, b[nf]);
        }
        __syncthreads();
    }

#pragma unroll
    for (int half = 0; half < 2; half++) {
        int row = rowBase + wid * 16 + g + half * 8;
        float v[5][2];
#pragma unroll
        for (int nf = 0; nf < 5; nf++) {
            int col = nf * 8 + 2 * tg;
            v[nf][0] = c[nf][2 * half]     + sb[col];
            v[nf][1] = c[nf][2 * half + 1] + sb[col + 1];
        }
        float mx = -1e30f;
#pragma unroll
        for (int nf = 0; nf < 5; nf++)
            mx = fmaxf(mx, fmaxf(v[nf][0], v[nf][1]));
        mx = fmaxf(mx, __shfl_xor_sync(0xffffffffu, mx, 1));
        mx = fmaxf(mx, __shfl_xor_sync(0xffffffffu, mx, 2));
        float s = 0.f;
#pragma unroll
        for (int nf = 0; nf < 5; nf++)
            s += expf(v[nf][0] - mx) + expf(v[nf][1] - mx);
        s += __shfl_xor_sync(0xffffffffu, s, 1);
        s += __shfl_xor_sync(0xffffffffu, s, 2);
        float lse = logf(s) + mx;
        if (row < N_NODES) {
#pragma unroll
            for (int nf = 0; nf < 5; nf++) {
                float2 o = make_float2(v[nf][0] - lse, v[nf][1] - lse);
                *(float2*)(out + row * 40 + nf * 8 + 2 * tg) = o;
            }
        }
    }
}

// ---------------------------------------------------------------------------
// Launch (order chosen so ncu's `-s 5 -c 1` captures aggregate_kernel)
// ---------------------------------------------------------------------------
extern "C" void kernel_launch(void* const* d_in, const int* in_sizes, int n_in,
                              void* d_out, int out_size) {
    const float* x   = (const float*)d_in[0];
    const int*   ei  = (const int*)d_in[1];
    const float* Wl0 = (const float*)d_in[2];
    const float* Wr0 = (const float*)d_in[3];
    const float* b0  = (const float*)d_in[4];
    const float* Wl1 = (const float*)d_in[5];
    const float* Wr1 = (const float*)d_in[6];
    const float* b1  = (const float*)d_in[7];
    const float* Wl2 = (const float*)d_in[8];
    const float* Wr2 = (const float*)d_in[9];
    const float* b2  = (const float*)d_in[10];
    float* out = (float*)d_out;

    const int GN  = (N_NODES + 255) / 256;
    const int GE  = (N_EDGES + 255) / 256;
    const int GW  = (N_NODES * 32 + 255) / 256;       // warp per node
    const int GT  = (N_NODES + 127) / 128;            // TC GEMM blocks

    // CSR build: 5 launches (0..4)
    zero_detect_kernel<<<GN, 256>>>(ei);
    count_deg_kernel  <<<GE, 256>>>(ei);
    scan_blocks_kernel<<<SCAN_NBLK, 256>>>();
    scan_add_kernel   <<<GN, 256>>>();
    fill_csr_kernel   <<<GE, 256>>>(ei);

    // Layer 0 (aggregate = launch index 5 -> profiled)
    aggregate_kernel      <<<GW, 256>>>(x, 0);
    dual_gemm128_tc_kernel<<<GT, 256>>>(x, 0, Wl0, Wr0, b0, /*out=g_h*/1);

    // Layer 1
    aggregate_kernel      <<<GW, 256>>>(nullptr, 1);
    dual_gemm128_tc_kernel<<<GT, 256>>>(nullptr, 1, Wl1, Wr1, b1, /*out=g_h2*/2);

    // Layer 2: tensor-core dual GEMM + fused log_softmax
    aggregate_kernel      <<<GW, 256>>>(nullptr, 2);
    dual_gemm40_tc_lsm_kernel<<<GT, 256>>>(Wl2, Wr2, b2, out);
}

// round 17
// speedup vs baseline: 1.0826x; 1.0826x over previous
#include <cuda_runtime.h>
#include <cuda_bf16.h>
#include <math.h>

// Problem constants
#define N_NODES 100000
#define N_EDGES 1600000
#define DFEAT   128
#define NCLS    40

// ---------------------------------------------------------------------------
// Device scratch (no allocations allowed). All zero-initialized at load.
// ---------------------------------------------------------------------------
__device__ __align__(16) float g_aggr[N_NODES * DFEAT];
__device__ __align__(16) float g_h   [N_NODES * DFEAT];
__device__ __align__(16) float g_h2  [N_NODES * DFEAT];
__device__ int   g_deg   [N_NODES];       // zero-init; re-zeroed by scan kernel
__device__ float g_deginv[N_NODES];
__device__ int   g_rowptr[N_NODES + 1];
__device__ int   g_cursor[N_NODES];
__device__ int   g_csr   [N_EDGES];
__device__ int   g_blocksum[128];
__device__ int   g_scan_done;             // zero-init; reset by fill_csr

#define SCAN_NBLK ((N_NODES + 1023) / 1024)   // 98

// ---------------------------------------------------------------------------
// CSR build, 3 launches. Edge index layout is int32 (proven: int64 read
// trapped in R10; runtime detection in R11..R16 always selected int32).
// ---------------------------------------------------------------------------
__global__ void count_deg_kernel(const int* __restrict__ ei) {
    int e = blockIdx.x * blockDim.x + threadIdx.x;
    if (e < N_EDGES) {
        int dst = ei[N_EDGES + e];
        if ((unsigned)dst < (unsigned)N_NODES)
            atomicAdd(&g_deg[dst], 1);
    }
}

// Fused scan: 98 blocks, each scans 1024 degs; block sums exchanged through
// global memory with a publish counter (all blocks co-resident -> spin safe).
// Also computes deginv + cursor and re-zeros g_deg for the next invocation.
__global__ void scan_fused_kernel() {
    __shared__ int wsum[8];
    __shared__ int s_off;
    int tid  = threadIdx.x;
    int bid  = blockIdx.x;
    int base = bid * 1024 + tid * 4;
    int v[4];
    int s = 0;
#pragma unroll
    for (int j = 0; j < 4; j++) {
        v[j] = (base + j < N_NODES) ? g_deg[base + j] : 0;
        s += v[j];
    }
    int lane = tid & 31, w = tid >> 5;
    int inc = s;
#pragma unroll
    for (int o = 1; o < 32; o <<= 1) {
        int y = __shfl_up_sync(0xffffffffu, inc, o);
        if (lane >= o) inc += y;
    }
    if (lane == 31) wsum[w] = inc;
    __syncthreads();
    if (w == 0) {
        int t = (lane < 8) ? wsum[lane] : 0;
#pragma unroll
        for (int o = 1; o < 8; o <<= 1) {
            int y = __shfl_up_sync(0xffffffffu, t, o);
            if (lane >= o) t += y;
        }
        if (lane < 8) wsum[lane] = t;
    }
    __syncthreads();
    int excl = inc - s + (w ? wsum[w - 1] : 0);   // block-local exclusive prefix

    // Publish block total, wait for all 98, compute block offset.
    if (tid == 0) {
        g_blocksum[bid] = wsum[7];
        __threadfence();
        atomicAdd(&g_scan_done, 1);
        while (atomicAdd(&g_scan_done, 0) < SCAN_NBLK) { }
        __threadfence();
        int off = 0;
        for (int j = 0; j < bid; j++) off += g_blocksum[j];
        s_off = off;
    }
    __syncthreads();
    int off = s_off;

#pragma unroll
    for (int j = 0; j < 4; j++) {
        int i = base + j;
        if (i < N_NODES) {
            int r = excl + off;
            g_rowptr[i] = r;
            g_cursor[i] = r;
            g_deginv[i] = 1.0f / (float)max(v[j], 1);
            g_deg[i] = 0;                          // ready for next call
            if (i == N_NODES - 1) g_rowptr[N_NODES] = r + v[j];
        }
        excl += v[j];
    }
}

__global__ void fill_csr_kernel(const int* __restrict__ ei) {
    int e = blockIdx.x * blockDim.x + threadIdx.x;
    if (e == 0) g_scan_done = 0;                   // reset for next call
    if (e < N_EDGES) {
        int dst = ei[N_EDGES + e];
        if ((unsigned)dst < (unsigned)N_NODES) {
            int src = ei[e];
            if ((unsigned)src >= (unsigned)N_NODES) src = 0;
            int pos = atomicAdd(&g_cursor[dst], 1);
            g_csr[pos] = src;
        }
    }
}

// ---------------------------------------------------------------------------
// Feature source selection
// ---------------------------------------------------------------------------
__device__ __forceinline__ const float* pick_feat(const float* ext, int sel) {
    return sel == 0 ? ext : (sel == 1 ? g_h : g_h2);
}

// ---------------------------------------------------------------------------
// Mean aggregation: one warp per node, lane owns 4 contiguous floats.
// (R15 version — the R16 batching experiment regressed.)
// ---------------------------------------------------------------------------
__global__ void aggregate_kernel(const float* __restrict__ feat_ext, int sel) {
    int gw = (blockIdx.x * blockDim.x + threadIdx.x) >> 5;
    if (gw >= N_NODES) return;
    const float* feat = pick_feat(feat_ext, sel);
    int lane = threadIdx.x & 31;
    int s = g_rowptr[gw];
    int e = g_rowptr[gw + 1];
    float4 acc = make_float4(0.f, 0.f, 0.f, 0.f);
    const float4* f4 = (const float4*)feat;
    for (int b = s; b < e; b += 32) {
        int idx = 0;
        if (b + lane < e) idx = g_csr[b + lane];
        int cnt = min(32, e - b);
#pragma unroll 4
        for (int t = 0; t < cnt; t++) {
            int src = __shfl_sync(0xffffffffu, idx, t);
            float4 v = __ldg(&f4[src * 32 + lane]);
            acc.x += v.x; acc.y += v.y; acc.z += v.z; acc.w += v.w;
        }
    }
    float di = g_deginv[gw];
    acc.x *= di; acc.y *= di; acc.z *= di; acc.w *= di;
    ((float4*)g_aggr)[gw * 32 + lane] = acc;
}

// ---------------------------------------------------------------------------
// tf32 mma (raw fp32 bits fed as tf32: HW ignores low mantissa bits)
// ---------------------------------------------------------------------------
__device__ __forceinline__ void mma_tf32(float c[4], const float a[4], const float b[2]) {
    asm volatile(
        "mma.sync.aligned.m16n8k8.row.col.f32.tf32.tf32.f32 "
        "{%0,%1,%2,%3}, {%4,%5,%6,%7}, {%8,%9}, {%0,%1,%2,%3};\n"
        : "+f"(c[0]), "+f"(c[1]), "+f"(c[2]), "+f"(c[3])
        : "r"(__float_as_uint(a[0])), "r"(__float_as_uint(a[1])),
          "r"(__float_as_uint(a[2])), "r"(__float_as_uint(a[3])),
          "r"(__float_as_uint(b[0])), "r"(__float_as_uint(b[1])));
}

// ---------------------------------------------------------------------------
// Tensor-core dual GEMM, D=128 -> 128 as one K=256 GEMM (pipelined fills).
// ---------------------------------------------------------------------------
__global__ __launch_bounds__(256) void dual_gemm128_tc_kernel(
    const float* __restrict__ Ax_ext, int ax_sel,
    const float* __restrict__ Wl, const float* __restrict__ Wr,
    const float* __restrict__ bias, int out_sel)
{
    __shared__ float sA[128 * 36];
    __shared__ float sB[32 * 132];

    const float* Ax  = pick_feat(Ax_ext, ax_sel);
    float* out = (out_sel == 1) ? g_h : g_h2;

    int tid  = threadIdx.x;
    int wid  = tid >> 5;
    int lane = tid & 31;
    int wm   = wid & 1;
    int wn   = wid >> 1;
    int tg   = lane & 3;
    int g    = lane >> 2;
    int rowBase = blockIdx.x * 128;

    int ra[4], ca[4], rb[4], cb[4];
#pragma unroll
    for (int i = 0; i < 4; i++) {
        int q = tid + i * 256;
        ra[i] = q >> 3; ca[i] = q & 7;
        rb[i] = q >> 5; cb[i] = q & 31;
    }

    float c[4][4][4];
#pragma unroll
    for (int mf = 0; mf < 4; mf++)
#pragma unroll
        for (int nf = 0; nf < 4; nf++)
#pragma unroll
            for (int i = 0; i < 4; i++) c[mf][nf][i] = 0.f;

    float4 pa[4], pb[4];
    {
#pragma unroll
        for (int i = 0; i < 4; i++) {
            int row = rowBase + ra[i];
            pa[i] = make_float4(0.f, 0.f, 0.f, 0.f);
            if (row < N_NODES)
                pa[i] = __ldg((const float4*)(g_aggr + row * 128) + ca[i]);
            pb[i] = __ldg((const float4*)(Wl + rb[i] * 128) + cb[i]);
        }
    }

    for (int kc = 0; kc < 256; kc += 32) {
#pragma unroll
        for (int i = 0; i < 4; i++) {
            *(float4*)&sA[ra[i] * 36 + ca[i] * 4] = pa[i];
            *(float4*)&sB[rb[i] * 132 + cb[i] * 4] = pb[i];
        }
        __syncthreads();

        int kn = kc + 32;
        if (kn < 256) {
            const float* srcA = (kn < 128) ? g_aggr : Ax;
            const float* srcW = (kn < 128) ? Wl : Wr;
            int knl = kn & 127;
#pragma unroll
            for (int i = 0; i < 4; i++) {
                int row = rowBase + ra[i];
                pa[i] = make_float4(0.f, 0.f, 0.f, 0.f);
                if (row < N_NODES)
                    pa[i] = __ldg((const float4*)(srcA + row * 128 + knl) + ca[i]);
                pb[i] = __ldg((const float4*)(srcW + (knl + rb[i]) * 128) + cb[i]);
            }
        }

#pragma unroll
        for (int kk = 0; kk < 32; kk += 8) {
            float a[4][4];
#pragma unroll
            for (int mf = 0; mf < 4; mf++) {
                int r0 = (wm * 64 + mf * 16 + g) * 36 + kk + tg;
                a[mf][0] = sA[r0];
                a[mf][1] = sA[r0 + 8 * 36];
                a[mf][2] = sA[r0 + 4];
                a[mf][3] = sA[r0 + 8 * 36 + 4];
            }
            float b[4][2];
#pragma unroll
            for (int nf = 0; nf < 4; nf++) {
                int col = wn * 32 + nf * 8 + g;
                b[nf][0] = sB[(kk + tg) * 132 + col];
                b[nf][1] = sB[(kk + tg + 4) * 132 + col];
            }
#pragma unroll
            for (int mf = 0; mf < 4; mf++)
#pragma unroll
                for (int nf = 0; nf < 4; nf++)
                    mma_tf32(c[mf][nf], a[mf], b[nf]);
        }
        __syncthreads();
    }

#pragma unroll
    for (int mf = 0; mf < 4; mf++) {
        int row0 = rowBase + wm * 64 + mf * 16 + g;
#pragma unroll
        for (int nf = 0; nf < 4; nf++) {
            int col = wn * 32 + nf * 8 + 2 * tg;
            float2 bv = __ldg((const float2*)(bias + col));
            if (row0 < N_NODES) {
                float2 o;
                o.x = fmaxf(c[mf][nf][0] + bv.x, 0.f);
                o.y = fmaxf(c[mf][nf][1] + bv.y, 0.f);
                *(float2*)(out + row0 * 128 + col) = o;
            }
            if (row0 + 8 < N_NODES) {
                float2 o;
                o.x = fmaxf(c[mf][nf][2] + bv.x, 0.f);
                o.y = fmaxf(c[mf][nf][3] + bv.y, 0.f);
                *(float2*)(out + (row0 + 8) * 128 + col) = o;
            }
        }
    }
}

// ---------------------------------------------------------------------------
// Tensor-core dual GEMM, D=128 -> 40 + fused log_softmax (final layer).
// ---------------------------------------------------------------------------
__global__ __launch_bounds__(256) void dual_gemm40_tc_lsm_kernel(
    const float* __restrict__ Wl, const float* __restrict__ Wr,
    const float* __restrict__ bias, float* __restrict__ out)
{
    __shared__ float sA[128 * 36];
    __shared__ float sB[32 * 44];
    __shared__ float sb[40];

    int tid  = threadIdx.x;
    int wid  = tid >> 5;
    int lane = tid & 31;
    int tg   = lane & 3;
    int g    = lane >> 2;
    int rowBase = blockIdx.x * 128;
    if (tid < 40) sb[tid] = __ldg(bias + tid);

    int ra[4], ca[4];
#pragma unroll
    for (int i = 0; i < 4; i++) {
        int q = tid + i * 256;
        ra[i] = q >> 3; ca[i] = q & 7;
    }
    int qk[5], qj[5];
#pragma unroll
    for (int i = 0; i < 5; i++) {
        int q = tid + i * 256;
        qk[i] = q / 40; qj[i] = q - qk[i] * 40;
    }

    float c[5][4];
#pragma unroll
    for (int nf = 0; nf < 5; nf++)
#pragma unroll
        for (int i = 0; i < 4; i++) c[nf][i] = 0.f;

    float4 pa[4];
    float  pbv[5];
    {
#pragma unroll
        for (int i = 0; i < 4; i++) {
            int row = rowBase + ra[i];
            pa[i] = make_float4(0.f, 0.f, 0.f, 0.f);
            if (row < N_NODES)
                pa[i] = __ldg((const float4*)(g_aggr + row * 128) + ca[i]);
        }
#pragma unroll
        for (int i = 0; i < 5; i++)
            pbv[i] = __ldg(Wl + qk[i] * 40 + qj[i]);
    }

    for (int kc = 0; kc < 256; kc += 32) {
#pragma unroll
        for (int i = 0; i < 4; i++)
            *(float4*)&sA[ra[i] * 36 + ca[i] * 4] = pa[i];
#pragma unroll
        for (int i = 0; i < 5; i++)
            sB[qk[i] * 44 + qj[i]] = pbv[i];
        __syncthreads();

        int kn = kc + 32;
        if (kn < 256) {
            const float* srcA = (kn < 128) ? g_aggr : g_h2;
            const float* srcW = (kn < 128) ? Wl : Wr;
            int knl = kn & 127;
#pragma unroll
            for (int i = 0; i < 4; i++) {
                int row = rowBase + ra[i];
                pa[i] = make_float4(0.f, 0.f, 0.f, 0.f);
                if (row < N_NODES)
                    pa[i] = __ldg((const float4*)(srcA + row * 128 + knl) + ca[i]);
            }
#pragma unroll
            for (int i = 0; i < 5; i++)
                pbv[i] = __ldg(srcW + (knl + qk[i]) * 40 + qj[i]);
        }

#pragma unroll
        for (int kk = 0; kk < 32; kk += 8) {
            float a[4];
            {
                int r0 = (wid * 16 + g) * 36 + kk + tg;
                a[0] = sA[r0];
                a[1] = sA[r0 + 8 * 36];
                a[2] = sA[r0 + 4];
                a[3] = sA[r0 + 8 * 36 + 4];
            }
            float b[5][2];
#pragma unroll
            for (int nf = 0; nf < 5; nf++) {
                int col = nf * 8 + g;
                b[nf][0] = sB[(kk + tg) * 44 + col];
                b[nf][1] = sB[(kk + tg + 4) * 44 + col];
            }
#pragma unroll
            for (int nf = 0; nf < 5; nf++)
                mma_tf32(c[nf], a, b[nf]);
        }
        __syncthreads();
    }

#pragma unroll
    for (int half = 0; half < 2; half++) {
        int row = rowBase + wid * 16 + g + half * 8;
        float v[5][2];
#pragma unroll
        for (int nf = 0; nf < 5; nf++) {
            int col = nf * 8 + 2 * tg;
            v[nf][0] = c[nf][2 * half]     + sb[col];
            v[nf][1] = c[nf][2 * half + 1] + sb[col + 1];
        }
        float mx = -1e30f;
#pragma unroll
        for (int nf = 0; nf < 5; nf++)
            mx = fmaxf(mx, fmaxf(v[nf][0], v[nf][1]));
        mx = fmaxf(mx, __shfl_xor_sync(0xffffffffu, mx, 1));
        mx = fmaxf(mx, __shfl_xor_sync(0xffffffffu, mx, 2));
        float s = 0.f;
#pragma unroll
        for (int nf = 0; nf < 5; nf++)
            s += expf(v[nf][0] - mx) + expf(v[nf][1] - mx);
        s += __shfl_xor_sync(0xffffffffu, s, 1);
        s += __shfl_xor_sync(0xffffffffu, s, 2);
        float lse = logf(s) + mx;
        if (row < N_NODES) {
#pragma unroll
            for (int nf = 0; nf < 5; nf++) {
                float2 o = make_float2(v[nf][0] - lse, v[nf][1] - lse);
                *(float2*)(out + row * 40 + nf * 8 + 2 * tg) = o;
            }
        }
    }
}

// ---------------------------------------------------------------------------
// Launch (aggregate_kernel is the 4th launch -> lands in the ncu window)
// ---------------------------------------------------------------------------
extern "C" void kernel_launch(void* const* d_in, const int* in_sizes, int n_in,
                              void* d_out, int out_size) {
    const float* x   = (const float*)d_in[0];
    const int*   ei  = (const int*)d_in[1];
    const float* Wl0 = (const float*)d_in[2];
    const float* Wr0 = (const float*)d_in[3];
    const float* b0  = (const float*)d_in[4];
    const float* Wl1 = (const float*)d_in[5];
    const float* Wr1 = (const float*)d_in[6];
    const float* b1  = (const float*)d_in[7];
    const float* Wl2 = (const float*)d_in[8];
    const float* Wr2 = (const float*)d_in[9];
    const float* b2  = (const float*)d_in[10];
    float* out = (float*)d_out;

    const int GE  = (N_EDGES + 255) / 256;
    const int GW  = (N_NODES * 32 + 255) / 256;       // warp per node
    const int GT  = (N_NODES + 127) / 128;            // TC GEMM blocks

    // CSR build: 3 launches (g_deg pre-zeroed; scan re-zeros it each call)
    count_deg_kernel<<<GE, 256>>>(ei);                // 0
    scan_fused_kernel<<<SCAN_NBLK, 256>>>();          // 1
    fill_csr_kernel <<<GE, 256>>>(ei);                // 2

    // Layer 0 (aggregate = 4th launch -> profiled)
    aggregate_kernel      <<<GW, 256>>>(x, 0);        // 3
    dual_gemm128_tc_kernel<<<GT, 256>>>(x, 0, Wl0, Wr0, b0, /*out=g_h*/1);

    // Layer 1
    aggregate_kernel      <<<GW, 256>>>(nullptr, 1);
    dual_gemm128_tc_kernel<<<GT, 256>>>(nullptr, 1, Wl1, Wr1, b1, /*out=g_h2*/2);

    // Layer 2: tensor-core dual GEMM + fused log_softmax
    aggregate_kernel      <<<GW, 256>>>(nullptr, 2);
    dual_gemm40_tc_lsm_kernel<<<GT, 256>>>(Wl2, Wr2, b2, out);
}